// round 14
// baseline (speedup 1.0000x reference)
#include <cuda_runtime.h>
#include <cuda_bf16.h>
#include <math.h>
#include <cstdint>

#define Tn 30
#define DTC 0.03f
#define NB 128
#define NT 512

// ---- smem layout ----
// LSTM phase (bytes): A buf0 [0,22528), A buf1 [22528,45056), B hi [45056,90112)
//   (rows 176B, K=80: cols 0-63 = h, 64-67 = input, 68 = 1.0/bias, 69-79 = 0)
// MLP overlay (floats): MLPW @0 (19456), ZB @19456 (13824), STASH @33280 (8192)
// Tail (floats): WC @41472 (160), PART @41632 (1024), HST @42656 (8704)
#define AROW_B  176
#define ABUF_B  22528      // bytes per A buffer
#define BHI_BY  45056      // B byte offset
#define BHI_F   11264
#define MLPW_F  0
#define ZB2_F   19456
#define STASH_F 33280
#define WC_F    41472
#define PART_F  41632
#define HST_F   42656
#define SM_FLOATS 51360
#define SMEM_BYTES (SM_FLOATS*4)

#define STRIDE_H 68
#define STRIDE_Z 108

#define N_REC  (16384*120)
#define OFF_EXP 1966080
#define OFF_MU  3932160
#define OFF_LV  5570560

typedef unsigned long long u64;

// ---- PTX helpers ----
__device__ __forceinline__ uint32_t smem_to_u32(const void* p){
    uint32_t a;
    asm("{ .reg .u64 t; cvta.to.shared.u64 t, %1; cvt.u32.u64 %0, t; }" : "=r"(a) : "l"(p));
    return a;
}
__device__ __forceinline__ void ldm4(uint32_t* r, uint32_t addr){
    asm volatile("ldmatrix.sync.aligned.m8n8.x4.shared.b16 {%0,%1,%2,%3}, [%4];"
        : "=r"(r[0]), "=r"(r[1]), "=r"(r[2]), "=r"(r[3]) : "r"(addr));
}
__device__ __forceinline__ void mma_bf16(float* d, const uint32_t* a, uint32_t b0, uint32_t b1){
    asm volatile("mma.sync.aligned.m16n8k16.row.col.f32.bf16.bf16.f32 "
        "{%0,%1,%2,%3}, {%4,%5,%6,%7}, {%8,%9}, {%0,%1,%2,%3};"
        : "+f"(d[0]), "+f"(d[1]), "+f"(d[2]), "+f"(d[3])
        : "r"(a[0]), "r"(a[1]), "r"(a[2]), "r"(a[3]), "r"(b0), "r"(b1));
}

// ---- fast activations ----
__device__ __forceinline__ float tanh_hw(float x){
    float y; asm("tanh.approx.f32 %0, %1;" : "=f"(y) : "f"(x)); return y;
}
__device__ __forceinline__ float sig_hw(float x){
    return fmaf(tanh_hw(0.5f*x), 0.5f, 0.5f);
}

// ---- fma2 helpers (MLP path) ----
__device__ __forceinline__ u64 fma2(u64 a, u64 b, u64 c){
    u64 d; asm("fma.rn.f32x2 %0, %1, %2, %3;" : "=l"(d) : "l"(a), "l"(b), "l"(c)); return d;
}
__device__ __forceinline__ void unpack2(u64 a, float& lo, float& hi){
    asm("mov.b64 {%0, %1}, %2;" : "=f"(lo), "=f"(hi) : "l"(a));
}
__device__ __forceinline__ float hsum2(u64 a){ float lo, hi; unpack2(a, lo, hi); return lo + hi; }

__device__ __forceinline__ float tanhfast(float x){   // precise (z sampling only)
    x = fminf(fmaxf(x, -15.0f), 15.0f);
    float e = __expf(2.0f*x);
    return __fdividef(e - 1.0f, e + 1.0f);
}
__device__ __forceinline__ float leaky(float x){ return x >= 0.0f ? x : 0.01f*x; }

__device__ __forceinline__ void cpw(float* dst, const float* src, int n){
    for (int i = threadIdx.x*4; i < n; i += NT*4)
        *(float4*)(dst+i) = *(const float4*)(src+i);
}
__device__ __forceinline__ uint32_t pkbf2(float a, float b){
    __nv_bfloat162 t = __floats2bfloat162_rn(a, b);
    return *reinterpret_cast<uint32_t*>(&t);
}

// Build B tile in smem straight from fp32 globals:
// W_hh [256][64] -> bf16, 176B-stride rows; ext cols 64-67 = folded input
// weights (W_ih@W_se), col 68 = folded bias, 69-79 = 0.
__device__ __forceinline__ void buildB(float* sm,
    const float* __restrict__ Whh, const float* __restrict__ Wih,
    const float* __restrict__ Wse, const float* __restrict__ bse,
    const float* __restrict__ bih, const float* __restrict__ bhh)
{
    float* bH = sm + BHI_F;
    for (int c = threadIdx.x; c < 2048; c += NT) {
        int n = c >> 3, cc = c & 7;
        const float4* s = (const float4*)(Whh + n*64 + cc*8);
        float4 x = s[0], y = s[1];
        *(uint4*)(bH + n*44 + cc*4) =
            make_uint4(pkbf2(x.x,x.y), pkbf2(x.z,x.w), pkbf2(y.x,y.y), pkbf2(y.z,y.w));
    }
    for (int n = threadIdx.x; n < 256; n += NT) {
        float w0=0.f, w1=0.f, w2=0.f, w3=0.f, b=0.f;
        const float* wr = Wih + n*64;
        #pragma unroll 4
        for (int e = 0; e < 64; ++e) {
            float wih = wr[e];
            w0 = fmaf(wih, Wse[e*4+0], w0);
            w1 = fmaf(wih, Wse[e*4+1], w1);
            w2 = fmaf(wih, Wse[e*4+2], w2);
            w3 = fmaf(wih, Wse[e*4+3], w3);
            b  = fmaf(wih, bse[e], b);
        }
        b += bih[n] + bhh[n];
        *(uint4*)(bH + n*44 + 32) = make_uint4(pkbf2(w0,w1), pkbf2(w2,w3), pkbf2(b,0.f), 0u);
        *(uint4*)(bH + n*44 + 36) = make_uint4(0,0,0,0);
    }
}

// zero both A buffers, set col68 = 1.0
__device__ __forceinline__ void initA(float* sm, char* smc){
    for (int i = threadIdx.x*4; i < 11264; i += NT*4)
        *(float4*)(sm + i) = make_float4(0.f,0.f,0.f,0.f);
    __syncthreads();
    if (threadIdx.x < 128) {
        uint32_t one = pkbf2(1.0f, 0.f);
        *(uint32_t*)(smc + threadIdx.x*AROW_B + 136) = one;
        *(uint32_t*)(smc + ABUF_B + threadIdx.x*AROW_B + 136) = one;
    }
}

// stage per-row input into A buffer cols 64..67 (bf16)
__device__ __forceinline__ void stage_in(char* smc, int bufB, int row, float4 in){
    char* base = smc + bufB + row*AROW_B;
    *(uint32_t*)(base + 128) = pkbf2(in.x, in.y);
    *(uint32_t*)(base + 132) = pkbf2(in.z, in.w);
}

// ---- MLP helpers (fma2) ----
__device__ __forceinline__ float dot64(const u64 (&h2)[32], const float* __restrict__ wrow){
    const ulonglong2* w2 = (const ulonglong2*)wrow;
    u64 A = 0ULL, B = 0ULL;
    #pragma unroll
    for (int i = 0; i < 16; ++i) {
        ulonglong2 w = w2[i];
        A = fma2(h2[2*i],   w.x, A);
        B = fma2(h2[2*i+1], w.y, B);
    }
    return hsum2(A) + hsum2(B);
}
__device__ __forceinline__ void load_h2(u64 (&h2)[32], const float* __restrict__ hrow){
    const ulonglong2* hr = (const ulonglong2*)hrow;
    #pragma unroll
    for (int i = 0; i < 16; ++i) { ulonglong2 v = hr[i]; h2[2*i] = v.x; h2[2*i+1] = v.y; }
}
__device__ __forceinline__ void mlp_forward(const float* __restrict__ wb, u64 (&h2)[32],
                                            float* __restrict__ hrow, int u0, int q,
                                            float* __restrict__ zrow, float* __restrict__ gout,
                                            bool is_lv, const float* __restrict__ epsrow)
{
    const float* Ws = wb;
    const float* Wf = wb + 12288;
    const float* bs = wb + 18688;
    const float* bf = wb + 18880;
    #pragma unroll 1
    for (int l = 0; l < 3; ++l) {
        #pragma unroll 1
        for (int j = u0; j < u0+16; ++j)
            hrow[j] = leaky(dot64(h2, Ws + l*4096 + j*64) + bs[l*64 + j]);
        __syncthreads();
        load_h2(h2, hrow);
        __syncthreads();
    }
    #pragma unroll 1
    for (int j = q*25; j < q*25+25; ++j) {
        float v = leaky(dot64(h2, Wf + j*64) + bf[j]);
        gout[j] = v;
        if (!is_lv) zrow[j] = v;
        else {
            float e = epsrow[j];
            zrow[j] = tanhfast(fmaf(e, __expf(0.5f*v), zrow[j]));
        }
    }
}

// ================= single fused kernel =================
__global__ void __launch_bounds__(NT, 1) vae_kernel(
    const float* __restrict__ expert, const float* __restrict__ init_state, const float* __restrict__ eps,
    const float* __restrict__ W_se, const float* __restrict__ b_se,
    const float* __restrict__ W_ih_e, const float* __restrict__ W_hh_e,
    const float* __restrict__ b_ih_e, const float* __restrict__ b_hh_e,
    const float* __restrict__ mean_Ws, const float* __restrict__ mean_bs,
    const float* __restrict__ mean_Wf, const float* __restrict__ mean_bf,
    const float* __restrict__ lv_Ws, const float* __restrict__ lv_bs,
    const float* __restrict__ lv_Wf, const float* __restrict__ lv_bf,
    const float* __restrict__ W_init, const float* __restrict__ b_init,
    const float* __restrict__ W_ih_d, const float* __restrict__ W_hh_d,
    const float* __restrict__ b_ih_d, const float* __restrict__ b_hh_d,
    const float* __restrict__ W_c, const float* __restrict__ b_c,
    float* __restrict__ out)
{
    extern __shared__ float sm[];
    char* smc = (char*)sm;
    uint32_t smb = smem_to_u32(sm);
    const int tid = threadIdx.x;
    const int wid = tid >> 5, lane = tid & 31;
    const int gid = lane >> 2, tig = lane & 3;
    const int mq = wid & 3;          // m-tile of 32 rows
    const int nq = wid >> 2;         // u-block of 16 units

    // per-lane ldmatrix address components
    const int arow = (lane & 7) + ((lane >> 3) & 1)*8;
    const int ak8  = ((lane >> 4) & 1)*8;
    const int brow = (lane & 7) + ((lane >> 4) & 1)*8;
    const int bk8  = ((lane >> 3) & 1)*8;
    const uint32_t aB0H = smb + (uint32_t)((mq*32 + arow)*AROW_B + ak8*2);
    const uint32_t aB1H = aB0H + 16*AROW_B;
    const uint32_t bBase0 = smb + BHI_BY + (uint32_t)((nq*16 + brow)*AROW_B + bk8*2);

    float* part = sm + PART_F;

    // ---------------- fused setup: expert echo + encoder B tile ----------------
    {   // copy this block's expert slice to the output echo region
        const float4* s = (const float4*)(expert + (size_t)blockIdx.x*128*(Tn*4));
        float4* d = (float4*)(out + OFF_EXP + (size_t)blockIdx.x*128*(Tn*4));
        for (int i = tid; i < 128*Tn; i += NT) d[i] = s[i];
    }
    buildB(sm, W_hh_e, W_ih_e, W_se, b_se, b_ih_e, b_hh_e);
    initA(sm, smc);

    float cst[16];
    #pragma unroll
    for (int i = 0; i < 16; ++i) cst[i] = 0.0f;
    float px = 0.f, py = 0.f;
    const float4* trow = (tid < 128) ? (const float4*)(expert + (size_t)(blockIdx.x*128 + tid)*(Tn*4)) : nullptr;
    if (tid < 128) {
        float4 a = trow[0];
        stage_in(smc, 0, tid, a);
        px = a.x; py = a.y;
    }

    // ---------------- encoder loop (1 sync/step) ----------------
    #pragma unroll 1
    for (int t = 0; t < Tn; ++t) {
        __syncthreads();
        const int pB = (t & 1) * ABUF_B;
        const int qB = ABUF_B - pB;
        float acc[2][4][8];
        #pragma unroll
        for (int i = 0; i < 2; ++i)
            #pragma unroll
            for (int g = 0; g < 4; ++g)
                #pragma unroll
                for (int j = 0; j < 8; ++j) acc[i][g][j] = 0.f;
        #pragma unroll
        for (int kt = 0; kt < 5; ++kt) {
            uint32_t a0H[4], a1H[4];
            ldm4(a0H, aB0H + pB + kt*32);
            ldm4(a1H, aB1H + pB + kt*32);
            #pragma unroll
            for (int g = 0; g < 4; ++g) {
                uint32_t bH[4];
                ldm4(bH, bBase0 + (uint32_t)(g*64*AROW_B + kt*32));
                mma_bf16(&acc[0][g][0], a0H, bH[0], bH[1]);
                mma_bf16(&acc[0][g][4], a0H, bH[2], bH[3]);
                mma_bf16(&acc[1][g][0], a1H, bH[0], bH[1]);
                mma_bf16(&acc[1][g][4], a1H, bH[2], bH[3]);
            }
        }
        // epilogue -> other buffer
        #pragma unroll
        for (int mt = 0; mt < 2; ++mt) {
            #pragma unroll
            for (int rh = 0; rh < 2; ++rh) {
                int row = mq*32 + mt*16 + rh*8 + gid;
                #pragma unroll
                for (int j = 0; j < 2; ++j) {
                    float hh[2];
                    #pragma unroll
                    for (int e = 0; e < 2; ++e) {
                        int u = nq*16 + j*8 + 2*tig + e;
                        int fi = j*4 + rh*2 + e;
                        float ai = acc[mt][0][fi];
                        float af = acc[mt][1][fi];
                        float ag = acc[mt][2][fi];
                        float ao = acc[mt][3][fi];
                        int ci = mt*8 + rh*4 + j*2 + e;
                        float c = sig_hw(af)*cst[ci] + sig_hw(ai)*tanh_hw(ag);
                        cst[ci] = c;
                        float h = sig_hw(ao)*tanh_hw(c);
                        hh[e] = h;
                        if (t == Tn-1) sm[HST_F + row*STRIDE_H + u] = h;
                    }
                    int ub = nq*16 + j*8 + 2*tig;
                    *(uint32_t*)(smc + qB + row*AROW_B + ub*2) = pkbf2(hh[0], hh[1]);
                }
            }
        }
        if (tid < 128 && t < Tn-1) {
            float4 a = trow[t+1];
            float4 in = make_float4(a.x - px, a.y - py, a.z, a.w);
            px = a.x; py = a.y;
            stage_in(smc, qB, tid, in);
        }
    }
    __syncthreads();

    // ---------------- MLPs (fma2 path, overlay regions) ----------------
    const int r = tid & 127;
    const int q = tid >> 7;
    const int u0m = q * 16;
    const int grow = blockIdx.x*128 + r;
    u64 h2[32];

    load_h2(h2, sm + HST_F + r*STRIDE_H);
    __syncthreads();
    if (q == 0) {   // stash hT
        float* stash = sm + STASH_F + r*64;
        const float* hsrc = sm + HST_F + r*STRIDE_H;
        #pragma unroll
        for (int k = 0; k < 64; k += 4) *(float4*)(stash + k) = *(const float4*)(hsrc + k);
    }
    __syncthreads();

    cpw(sm + MLPW_F,         mean_Ws, 12288);
    cpw(sm + MLPW_F + 12288, mean_Wf, 6400);
    cpw(sm + MLPW_F + 18688, mean_bs, 192);
    cpw(sm + MLPW_F + 18880, mean_bf, 100);
    __syncthreads();
    mlp_forward(sm + MLPW_F, h2, sm + HST_F + r*STRIDE_H, u0m, q,
                sm + ZB2_F + r*STRIDE_Z, out + OFF_MU + (size_t)grow*100, false, nullptr);
    __syncthreads();

    load_h2(h2, sm + STASH_F + r*64);
    cpw(sm + MLPW_F,         lv_Ws, 12288);
    cpw(sm + MLPW_F + 12288, lv_Wf, 6400);
    cpw(sm + MLPW_F + 18688, lv_bs, 192);
    cpw(sm + MLPW_F + 18880, lv_bf, 100);
    __syncthreads();
    mlp_forward(sm + MLPW_F, h2, sm + HST_F + r*STRIDE_H, u0m, q,
                sm + ZB2_F + r*STRIDE_Z, out + OFF_LV + (size_t)grow*100, true, eps + (size_t)grow*100);
    __syncthreads();

    // dh = z @ W_init^T + b_init -> HST
    cpw(sm + MLPW_F,        W_init, 6400);
    cpw(sm + MLPW_F + 6400, b_init, 64);
    __syncthreads();
    {
        const ulonglong2* z2 = (const ulonglong2*)(sm + ZB2_F + r*STRIDE_Z);
        #pragma unroll 1
        for (int j = u0m; j < u0m+16; ++j) {
            const ulonglong2* w2 = (const ulonglong2*)(sm + MLPW_F + j*100);
            u64 A = 0ULL, B = 0ULL;
            #pragma unroll
            for (int i = 0; i < 25; ++i) {
                ulonglong2 w = w2[i], z = z2[i];
                A = fma2(z.x, w.x, A);
                B = fma2(z.y, w.y, B);
            }
            sm[HST_F + r*STRIDE_H + j] = hsum2(A) + hsum2(B) + sm[MLPW_F + 6400 + j];
        }
    }
    __syncthreads();

    // ---------------- decoder setup ----------------
    buildB(sm, W_hh_d, W_ih_d, W_se, b_se, b_ih_d, b_hh_d);
    initA(sm, smc);
    cpw(sm + WC_F, W_c, 128);
    if (tid == 0) { sm[WC_F+128] = b_c[0]; sm[WC_F+129] = b_c[1]; }
    __syncthreads();

    // c0 = h0 = dh; write A buf0 from HST; stage init_state
    float cst2[16];
    #pragma unroll
    for (int mt = 0; mt < 2; ++mt) {
        #pragma unroll
        for (int rh = 0; rh < 2; ++rh) {
            int row = mq*32 + mt*16 + rh*8 + gid;
            #pragma unroll
            for (int j = 0; j < 2; ++j) {
                int ub = nq*16 + j*8 + 2*tig;
                float h0 = sm[HST_F + row*STRIDE_H + ub];
                float h1 = sm[HST_F + row*STRIDE_H + ub + 1];
                cst2[mt*8 + rh*4 + j*2]     = h0;
                cst2[mt*8 + rh*4 + j*2 + 1] = h1;
                *(uint32_t*)(smc + row*AROW_B + ub*2) = pkbf2(h0, h1);
            }
        }
    }
    #pragma unroll
    for (int i = 0; i < 16; ++i) cst[i] = cst2[i];

    float4 prev;
    if (tid < 128) {
        prev = ((const float4*)init_state)[grow];
        stage_in(smc, 0, tid, prev);
    }
    const float* wc0 = sm + WC_F;
    const float* wc1 = sm + WC_F + 64;
    float* rec = out + (size_t)(blockIdx.x*128 + tid)*(Tn*4);   // valid for tid<128

    // ---------------- decoder loop ----------------
    #pragma unroll 1
    for (int t = 0; t < Tn; ++t) {
        __syncthreads();
        const int pB = (t & 1) * ABUF_B;
        const int qB = ABUF_B - pB;
        float acc[2][4][8];
        #pragma unroll
        for (int i = 0; i < 2; ++i)
            #pragma unroll
            for (int g = 0; g < 4; ++g)
                #pragma unroll
                for (int j = 0; j < 8; ++j) acc[i][g][j] = 0.f;
        #pragma unroll
        for (int kt = 0; kt < 5; ++kt) {
            uint32_t a0H[4], a1H[4];
            ldm4(a0H, aB0H + pB + kt*32);
            ldm4(a1H, aB1H + pB + kt*32);
            #pragma unroll
            for (int g = 0; g < 4; ++g) {
                uint32_t bH[4];
                ldm4(bH, bBase0 + (uint32_t)(g*64*AROW_B + kt*32));
                mma_bf16(&acc[0][g][0], a0H, bH[0], bH[1]);
                mma_bf16(&acc[0][g][4], a0H, bH[2], bH[3]);
                mma_bf16(&acc[1][g][0], a1H, bH[0], bH[1]);
                mma_bf16(&acc[1][g][4], a1H, bH[2], bH[3]);
            }
        }
        // epilogue: gates -> h, W_c partials, store other buffer
        float pa[8];
        #pragma unroll
        for (int i = 0; i < 8; ++i) pa[i] = 0.f;
        #pragma unroll
        for (int mt = 0; mt < 2; ++mt) {
            #pragma unroll
            for (int rh = 0; rh < 2; ++rh) {
                int row = mq*32 + mt*16 + rh*8 + gid;
                #pragma unroll
                for (int j = 0; j < 2; ++j) {
                    float hh[2];
                    #pragma unroll
                    for (int e = 0; e < 2; ++e) {
                        int u = nq*16 + j*8 + 2*tig + e;
                        int fi = j*4 + rh*2 + e;
                        float ai = acc[mt][0][fi];
                        float af = acc[mt][1][fi];
                        float ag = acc[mt][2][fi];
                        float ao = acc[mt][3][fi];
                        int ci = mt*8 + rh*4 + j*2 + e;
                        float c = sig_hw(af)*cst[ci] + sig_hw(ai)*tanh_hw(ag);
                        cst[ci] = c;
                        float h = sig_hw(ao)*tanh_hw(c);
                        hh[e] = h;
                        pa[(mt*2+rh)*2+0] = fmaf(h, wc0[u], pa[(mt*2+rh)*2+0]);
                        pa[(mt*2+rh)*2+1] = fmaf(h, wc1[u], pa[(mt*2+rh)*2+1]);
                    }
                    int ub = nq*16 + j*8 + 2*tig;
                    *(uint32_t*)(smc + qB + row*AROW_B + ub*2) = pkbf2(hh[0], hh[1]);
                }
            }
        }
        #pragma unroll
        for (int i = 0; i < 8; ++i) {
            pa[i] += __shfl_xor_sync(0xFFFFFFFFu, pa[i], 1);
            pa[i] += __shfl_xor_sync(0xFFFFFFFFu, pa[i], 2);
        }
        if (tig == 0) {
            #pragma unroll
            for (int mt = 0; mt < 2; ++mt) {
                #pragma unroll
                for (int rh = 0; rh < 2; ++rh) {
                    int row = mq*32 + mt*16 + rh*8 + gid;
                    part[row*8 + nq*2 + 0] = pa[(mt*2+rh)*2+0];
                    part[row*8 + nq*2 + 1] = pa[(mt*2+rh)*2+1];
                }
            }
        }
        __syncthreads();
        if (tid < 128) {
            float a0 = part[tid*8+0] + part[tid*8+2] + part[tid*8+4] + part[tid*8+6] + sm[WC_F+128];
            float a1 = part[tid*8+1] + part[tid*8+3] + part[tid*8+5] + part[tid*8+7] + sm[WC_F+129];
            float steer = fminf(fmaxf(a1, -0.5f), 0.5f);
            float x = prev.x, y = prev.y, psi = prev.z, v = prev.w;
            float v1 = fminf(fmaxf(fmaf(a0, DTC, v), 0.0f), 30.0f);
            float pd = fminf(fmaxf(v * __tanf(steer) * (1.0f/2.5f), -1.57f), 1.57f);
            float s, c; __sincosf(psi, &s, &c);
            float4 cur = make_float4(fmaf(v*c, DTC, x), fmaf(v*s, DTC, y), fmaf(pd, DTC, psi), v1);
            *(float4*)(rec + t*4) = cur;
            if (t < Tn-1) stage_in(smc, qB, tid, cur);
            prev = cur;
        }
    }
}

extern "C" void kernel_launch(void* const* d_in, const int* in_sizes, int n_in,
                              void* d_out, int out_size)
{
    const float* expert     = (const float*)d_in[0];
    const float* init_state = (const float*)d_in[1];
    const float* eps        = (const float*)d_in[2];
    const float* W_se       = (const float*)d_in[3];
    const float* b_se       = (const float*)d_in[4];
    const float* W_ih_e     = (const float*)d_in[5];
    const float* W_hh_e     = (const float*)d_in[6];
    const float* b_ih_e     = (const float*)d_in[7];
    const float* b_hh_e     = (const float*)d_in[8];
    const float* mean_Ws    = (const float*)d_in[9];
    const float* mean_bs    = (const float*)d_in[10];
    const float* mean_Wf    = (const float*)d_in[11];
    const float* mean_bf    = (const float*)d_in[12];
    const float* lv_Ws      = (const float*)d_in[13];
    const float* lv_bs      = (const float*)d_in[14];
    const float* lv_Wf      = (const float*)d_in[15];
    const float* lv_bf      = (const float*)d_in[16];
    const float* W_init     = (const float*)d_in[17];
    const float* b_init     = (const float*)d_in[18];
    const float* W_ih_d     = (const float*)d_in[19];
    const float* W_hh_d     = (const float*)d_in[20];
    const float* b_ih_d     = (const float*)d_in[21];
    const float* b_hh_d     = (const float*)d_in[22];
    const float* W_c        = (const float*)d_in[23];
    const float* b_c        = (const float*)d_in[24];
    float* out = (float*)d_out;

    cudaFuncSetAttribute(vae_kernel, cudaFuncAttributeMaxDynamicSharedMemorySize, SMEM_BYTES);

    vae_kernel<<<NB, NT, SMEM_BYTES>>>(expert, init_state, eps,
        W_se, b_se, W_ih_e, W_hh_e, b_ih_e, b_hh_e,
        mean_Ws, mean_bs, mean_Wf, mean_bf,
        lv_Ws, lv_bs, lv_Wf, lv_bf,
        W_init, b_init,
        W_ih_d, W_hh_d, b_ih_d, b_hh_d,
        W_c, b_c, out);
}

// round 17
// speedup vs baseline: 1.5667x; 1.5667x over previous
#include <cuda_runtime.h>
#include <cuda_bf16.h>
#include <math.h>
#include <cstdint>

#define Tn 30
#define DTC 0.03f
#define NB 128
#define NT 512

// ---- smem layout ----
// LSTM phase (bytes): A buf0 [0,22528), A buf1 [22528,45056), B hi [45056,90112)
//   (rows 176B, K=80: cols 0-63 = h, 64-67 = input, 68 = 1.0/bias, 69-79 = 0)
// MLP overlay (floats): MLPW @0 (19456), ZB @19456 (13824), STASH @33280 (8192)
// Tail (floats): WC @41472 (160), PART @41632 (1024), HST @42656 (8704)
#define AROW_B  176
#define ABUF_B  22528      // bytes per A buffer
#define BHI_BY  45056      // B byte offset
#define BHI_F   11264
#define MLPW_F  0
#define ZB2_F   19456
#define STASH_F 33280
#define WC_F    41472
#define PART_F  41632
#define HST_F   42656
#define SM_FLOATS 51360
#define SMEM_BYTES (SM_FLOATS*4)

#define STRIDE_H 68
#define STRIDE_Z 108

#define N_REC  (16384*120)
#define OFF_EXP 1966080
#define OFF_MU  3932160
#define OFF_LV  5570560

typedef unsigned long long u64;

// -------- persistent prepped weights --------
__device__ __align__(16) unsigned short g_Bhi_e[16384];  // bf16 of W_hh_e [256][64]
__device__ __align__(16) unsigned short g_Bhi_d[16384];
__device__ __align__(16) float g_wfp_e[1024];   // folded input weights [n*4+m], n=g*64+u
__device__ __align__(16) float g_bfp_e[256];    // folded bias [n]
__device__ __align__(16) float g_wfp_d[1024];
__device__ __align__(16) float g_bfp_d[256];

// ---- PTX helpers ----
__device__ __forceinline__ uint32_t smem_to_u32(const void* p){
    uint32_t a;
    asm("{ .reg .u64 t; cvta.to.shared.u64 t, %1; cvt.u32.u64 %0, t; }" : "=r"(a) : "l"(p));
    return a;
}
__device__ __forceinline__ void ldm4(uint32_t* r, uint32_t addr){
    asm volatile("ldmatrix.sync.aligned.m8n8.x4.shared.b16 {%0,%1,%2,%3}, [%4];"
        : "=r"(r[0]), "=r"(r[1]), "=r"(r[2]), "=r"(r[3]) : "r"(addr));
}
__device__ __forceinline__ void mma_bf16(float* d, const uint32_t* a, uint32_t b0, uint32_t b1){
    asm volatile("mma.sync.aligned.m16n8k16.row.col.f32.bf16.bf16.f32 "
        "{%0,%1,%2,%3}, {%4,%5,%6,%7}, {%8,%9}, {%0,%1,%2,%3};"
        : "+f"(d[0]), "+f"(d[1]), "+f"(d[2]), "+f"(d[3])
        : "r"(a[0]), "r"(a[1]), "r"(a[2]), "r"(a[3]), "r"(b0), "r"(b1));
}

// ---- fast activations ----
__device__ __forceinline__ float tanh_hw(float x){
    float y; asm("tanh.approx.f32 %0, %1;" : "=f"(y) : "f"(x)); return y;
}
__device__ __forceinline__ float sig_hw(float x){
    return fmaf(tanh_hw(0.5f*x), 0.5f, 0.5f);
}

// ---- fma2 helpers (MLP path) ----
__device__ __forceinline__ u64 fma2(u64 a, u64 b, u64 c){
    u64 d; asm("fma.rn.f32x2 %0, %1, %2, %3;" : "=l"(d) : "l"(a), "l"(b), "l"(c)); return d;
}
__device__ __forceinline__ void unpack2(u64 a, float& lo, float& hi){
    asm("mov.b64 {%0, %1}, %2;" : "=f"(lo), "=f"(hi) : "l"(a));
}
__device__ __forceinline__ float hsum2(u64 a){ float lo, hi; unpack2(a, lo, hi); return lo + hi; }

__device__ __forceinline__ float tanhfast(float x){   // precise (z sampling only)
    x = fminf(fmaxf(x, -15.0f), 15.0f);
    float e = __expf(2.0f*x);
    return __fdividef(e - 1.0f, e + 1.0f);
}
__device__ __forceinline__ float leaky(float x){ return x >= 0.0f ? x : 0.01f*x; }
__device__ __forceinline__ float bf16f(float v){ return __bfloat162float(__float2bfloat16(v)); }

__device__ __forceinline__ void cpw(float* dst, const float* src, int n){
    for (int i = threadIdx.x*4; i < n; i += NT*4)
        *(float4*)(dst+i) = *(const float4*)(src+i);
}
__device__ __forceinline__ uint32_t pkbf2(float a, float b){
    __nv_bfloat162 t = __floats2bfloat162_rn(a, b);
    return *reinterpret_cast<uint32_t*>(&t);
}

// copy [256][64] bf16 into 176B-stride rows + fill ext cols (input weights + bias)
__device__ __forceinline__ void cpBx(float* sm, const unsigned short* gHi,
                                     const float* wf, const float* bias){
    const uint4* sHi = (const uint4*)gHi;
    float* bH = sm + BHI_F;
    for (int c = threadIdx.x; c < 2048; c += NT) {
        int n = c >> 3, cc = c & 7;
        *(uint4*)(bH + n*44 + cc*4) = sHi[c];
    }
    for (int n = threadIdx.x; n < 256; n += NT) {
        float w0 = wf[n*4+0], w1 = wf[n*4+1], w2 = wf[n*4+2], w3 = wf[n*4+3];
        float b  = bias[n];
        *(uint4*)(bH + n*44 + 32) = make_uint4(pkbf2(w0,w1), pkbf2(w2,w3), pkbf2(b,0.f), 0u);
        *(uint4*)(bH + n*44 + 36) = make_uint4(0,0,0,0);
    }
}

// zero both A buffers, set col68 = 1.0
__device__ __forceinline__ void initA(float* sm, char* smc){
    for (int i = threadIdx.x*4; i < 11264; i += NT*4)
        *(float4*)(sm + i) = make_float4(0.f,0.f,0.f,0.f);
    __syncthreads();
    if (threadIdx.x < 128) {
        uint32_t one = pkbf2(1.0f, 0.f);
        *(uint32_t*)(smc + threadIdx.x*AROW_B + 136) = one;
        *(uint32_t*)(smc + ABUF_B + threadIdx.x*AROW_B + 136) = one;
    }
}

// stage per-row input into A buffer cols 64..67 (bf16)
__device__ __forceinline__ void stage_in(char* smc, int bufB, int row, float4 in){
    char* base = smc + bufB + row*AROW_B;
    *(uint32_t*)(base + 128) = pkbf2(in.x, in.y);
    *(uint32_t*)(base + 132) = pkbf2(in.z, in.w);
}

// ================ merged setup kernel: prep + expert echo copy ================
__global__ void setup_kernel(const float* __restrict__ W_se, const float* __restrict__ b_se,
    const float* __restrict__ W_ih_e, const float* __restrict__ W_hh_e,
    const float* __restrict__ b_ih_e, const float* __restrict__ b_hh_e,
    const float* __restrict__ W_ih_d, const float* __restrict__ W_hh_d,
    const float* __restrict__ b_ih_d, const float* __restrict__ b_hh_d,
    const float4* __restrict__ expert4, float4* __restrict__ echo4)
{
    int idx = blockIdx.x*blockDim.x + threadIdx.x;
    // echo copy (all 65536 threads, 7.5 float4 each)
    for (int i = idx; i < N_REC/4; i += gridDim.x*blockDim.x)
        echo4[i] = expert4[i];
    if (idx < 16384) {
        g_Bhi_e[idx] = __bfloat16_as_ushort(__float2bfloat16(W_hh_e[idx]));
        g_Bhi_d[idx] = __bfloat16_as_ushort(__float2bfloat16(W_hh_d[idx]));
    }
    if (idx < 1024) {
        int n = idx >> 2, m = idx & 3;
        float se = 0.f, sd = 0.f;
        for (int e = 0; e < 64; ++e) {
            se += W_ih_e[n*64+e] * W_se[e*4+m];
            sd += W_ih_d[n*64+e] * W_se[e*4+m];
        }
        g_wfp_e[idx] = se; g_wfp_d[idx] = sd;
    }
    if (idx < 256) {
        int n = idx;
        float se = 0.f, sd = 0.f;
        for (int e = 0; e < 64; ++e) {
            se += W_ih_e[n*64+e] * b_se[e];
            sd += W_ih_d[n*64+e] * b_se[e];
        }
        g_bfp_e[idx] = se + b_ih_e[n] + b_hh_e[n];
        g_bfp_d[idx] = sd + b_ih_d[n] + b_hh_d[n];
    }
}

// ---- MLP helpers (fma2) ----
__device__ __forceinline__ float dot64(const u64 (&h2)[32], const float* __restrict__ wrow){
    const ulonglong2* w2 = (const ulonglong2*)wrow;
    u64 A = 0ULL, B = 0ULL;
    #pragma unroll
    for (int i = 0; i < 16; ++i) {
        ulonglong2 w = w2[i];
        A = fma2(h2[2*i],   w.x, A);
        B = fma2(h2[2*i+1], w.y, B);
    }
    return hsum2(A) + hsum2(B);
}
__device__ __forceinline__ void load_h2(u64 (&h2)[32], const float* __restrict__ hrow){
    const ulonglong2* hr = (const ulonglong2*)hrow;
    #pragma unroll
    for (int i = 0; i < 16; ++i) { ulonglong2 v = hr[i]; h2[2*i] = v.x; h2[2*i+1] = v.y; }
}
__device__ __forceinline__ void mlp_forward(const float* __restrict__ wb, u64 (&h2)[32],
                                            float* __restrict__ hrow, int u0, int q,
                                            float* __restrict__ zrow, float* __restrict__ gout,
                                            bool is_lv, const float* __restrict__ epsrow)
{
    const float* Ws = wb;
    const float* Wf = wb + 12288;
    const float* bs = wb + 18688;
    const float* bf = wb + 18880;
    #pragma unroll 1
    for (int l = 0; l < 3; ++l) {
        #pragma unroll 1
        for (int j = u0; j < u0+16; ++j)
            hrow[j] = leaky(dot64(h2, Ws + l*4096 + j*64) + bs[l*64 + j]);
        __syncthreads();
        load_h2(h2, hrow);
        __syncthreads();
    }
    #pragma unroll 1
    for (int j = q*25; j < q*25+25; ++j) {
        float v = leaky(dot64(h2, Wf + j*64) + bf[j]);
        gout[j] = v;
        if (!is_lv) zrow[j] = v;
        else {
            float e = epsrow[j];
            zrow[j] = tanhfast(fmaf(e, __expf(0.5f*v), zrow[j]));
        }
    }
}

// ================= main kernel =================
__global__ void __launch_bounds__(NT, 1) vae_kernel(
    const float* __restrict__ expert, const float* __restrict__ init_state, const float* __restrict__ eps,
    const float* __restrict__ mean_Ws, const float* __restrict__ mean_bs,
    const float* __restrict__ mean_Wf, const float* __restrict__ mean_bf,
    const float* __restrict__ lv_Ws, const float* __restrict__ lv_bs,
    const float* __restrict__ lv_Wf, const float* __restrict__ lv_bf,
    const float* __restrict__ W_init, const float* __restrict__ b_init,
    const float* __restrict__ W_c, const float* __restrict__ b_c,
    float* __restrict__ out)
{
    extern __shared__ float sm[];
    char* smc = (char*)sm;
    uint32_t smb = smem_to_u32(sm);
    const int tid = threadIdx.x;
    const int wid = tid >> 5, lane = tid & 31;
    const int gid = lane >> 2, tig = lane & 3;
    const int mq = wid & 3;          // m-tile of 32 rows
    const int nq = wid >> 2;         // u-block of 16 units

    // per-lane ldmatrix address components
    const int arow = (lane & 7) + ((lane >> 3) & 1)*8;
    const int ak8  = ((lane >> 4) & 1)*8;
    const int brow = (lane & 7) + ((lane >> 4) & 1)*8;
    const int bk8  = ((lane >> 3) & 1)*8;
    const uint32_t aB0H = smb + (uint32_t)((mq*32 + arow)*AROW_B + ak8*2);
    const uint32_t aB1H = aB0H + 16*AROW_B;
    const uint32_t bBase0 = smb + BHI_BY + (uint32_t)((nq*16 + brow)*AROW_B + bk8*2);

    float* part = sm + PART_F;

    // ---------------- encoder setup ----------------
    cpBx(sm, g_Bhi_e, g_wfp_e, g_bfp_e);
    initA(sm, smc);

    float cst[16];
    #pragma unroll
    for (int i = 0; i < 16; ++i) cst[i] = 0.0f;
    float px = 0.f, py = 0.f;
    const float4* trow = (tid < 128) ? (const float4*)(expert + (size_t)(blockIdx.x*128 + tid)*(Tn*4)) : nullptr;
    if (tid < 128) {
        float4 a = trow[0];
        stage_in(smc, 0, tid, a);
        px = a.x; py = a.y;
    }

    // ---------------- encoder loop (1 sync/step) ----------------
    #pragma unroll 1
    for (int t = 0; t < Tn; ++t) {
        __syncthreads();
        const int pB = (t & 1) * ABUF_B;
        const int qB = ABUF_B - pB;
        float acc[2][4][8];
        #pragma unroll
        for (int i = 0; i < 2; ++i)
            #pragma unroll
            for (int g = 0; g < 4; ++g)
                #pragma unroll
                for (int j = 0; j < 8; ++j) acc[i][g][j] = 0.f;
        #pragma unroll
        for (int kt = 0; kt < 5; ++kt) {
            uint32_t a0H[4], a1H[4];
            ldm4(a0H, aB0H + pB + kt*32);
            ldm4(a1H, aB1H + pB + kt*32);
            #pragma unroll
            for (int g = 0; g < 4; ++g) {
                uint32_t bH[4];
                ldm4(bH, bBase0 + (uint32_t)(g*64*AROW_B + kt*32));
                mma_bf16(&acc[0][g][0], a0H, bH[0], bH[1]);
                mma_bf16(&acc[0][g][4], a0H, bH[2], bH[3]);
                mma_bf16(&acc[1][g][0], a1H, bH[0], bH[1]);
                mma_bf16(&acc[1][g][4], a1H, bH[2], bH[3]);
            }
        }
        // epilogue -> other buffer
        #pragma unroll
        for (int mt = 0; mt < 2; ++mt) {
            #pragma unroll
            for (int rh = 0; rh < 2; ++rh) {
                int row = mq*32 + mt*16 + rh*8 + gid;
                #pragma unroll
                for (int j = 0; j < 2; ++j) {
                    float hh[2];
                    #pragma unroll
                    for (int e = 0; e < 2; ++e) {
                        int u = nq*16 + j*8 + 2*tig + e;
                        int fi = j*4 + rh*2 + e;
                        float ai = acc[mt][0][fi];
                        float af = acc[mt][1][fi];
                        float ag = acc[mt][2][fi];
                        float ao = acc[mt][3][fi];
                        int ci = mt*8 + rh*4 + j*2 + e;
                        float c = sig_hw(af)*cst[ci] + sig_hw(ai)*tanh_hw(ag);
                        cst[ci] = c;
                        float h = sig_hw(ao)*tanh_hw(c);
                        hh[e] = h;
                        if (t == Tn-1) sm[HST_F + row*STRIDE_H + u] = h;
                    }
                    int ub = nq*16 + j*8 + 2*tig;
                    *(uint32_t*)(smc + qB + row*AROW_B + ub*2) = pkbf2(hh[0], hh[1]);
                }
            }
        }
        if (tid < 128 && t < Tn-1) {
            float4 a = trow[t+1];
            float4 in = make_float4(a.x - px, a.y - py, a.z, a.w);
            px = a.x; py = a.y;
            stage_in(smc, qB, tid, in);
        }
    }
    __syncthreads();

    // ---------------- MLPs (fma2 path, overlay regions) ----------------
    const int r = tid & 127;
    const int q = tid >> 7;
    const int u0m = q * 16;
    const int grow = blockIdx.x*128 + r;
    u64 h2[32];

    load_h2(h2, sm + HST_F + r*STRIDE_H);
    __syncthreads();
    if (q == 0) {   // stash hT
        float* stash = sm + STASH_F + r*64;
        const float* hsrc = sm + HST_F + r*STRIDE_H;
        #pragma unroll
        for (int k = 0; k < 64; k += 4) *(float4*)(stash + k) = *(const float4*)(hsrc + k);
    }
    __syncthreads();

    cpw(sm + MLPW_F,         mean_Ws, 12288);
    cpw(sm + MLPW_F + 12288, mean_Wf, 6400);
    cpw(sm + MLPW_F + 18688, mean_bs, 192);
    cpw(sm + MLPW_F + 18880, mean_bf, 100);
    __syncthreads();
    mlp_forward(sm + MLPW_F, h2, sm + HST_F + r*STRIDE_H, u0m, q,
                sm + ZB2_F + r*STRIDE_Z, out + OFF_MU + (size_t)grow*100, false, nullptr);
    __syncthreads();

    load_h2(h2, sm + STASH_F + r*64);
    cpw(sm + MLPW_F,         lv_Ws, 12288);
    cpw(sm + MLPW_F + 12288, lv_Wf, 6400);
    cpw(sm + MLPW_F + 18688, lv_bs, 192);
    cpw(sm + MLPW_F + 18880, lv_bf, 100);
    __syncthreads();
    mlp_forward(sm + MLPW_F, h2, sm + HST_F + r*STRIDE_H, u0m, q,
                sm + ZB2_F + r*STRIDE_Z, out + OFF_LV + (size_t)grow*100, true, eps + (size_t)grow*100);
    __syncthreads();

    // dh = z @ W_init^T + b_init -> HST
    cpw(sm + MLPW_F,        W_init, 6400);
    cpw(sm + MLPW_F + 6400, b_init, 64);
    __syncthreads();
    {
        const ulonglong2* z2 = (const ulonglong2*)(sm + ZB2_F + r*STRIDE_Z);
        #pragma unroll 1
        for (int j = u0m; j < u0m+16; ++j) {
            const ulonglong2* w2 = (const ulonglong2*)(sm + MLPW_F + j*100);
            u64 A = 0ULL, B = 0ULL;
            #pragma unroll
            for (int i = 0; i < 25; ++i) {
                ulonglong2 w = w2[i], z = z2[i];
                A = fma2(z.x, w.x, A);
                B = fma2(z.y, w.y, B);
            }
            sm[HST_F + r*STRIDE_H + j] = hsum2(A) + hsum2(B) + sm[MLPW_F + 6400 + j];
        }
    }
    __syncthreads();

    // ---------------- decoder setup ----------------
    cpBx(sm, g_Bhi_d, g_wfp_d, g_bfp_d);
    initA(sm, smc);
    cpw(sm + WC_F, W_c, 128);
    if (tid == 0) { sm[WC_F+128] = b_c[0]; sm[WC_F+129] = b_c[1]; }
    __syncthreads();

    // c0 = h0 = dh; write A buf0 from HST; stage init_state
    float cst2[16];
    #pragma unroll
    for (int mt = 0; mt < 2; ++mt) {
        #pragma unroll
        for (int rh = 0; rh < 2; ++rh) {
            int row = mq*32 + mt*16 + rh*8 + gid;
            #pragma unroll
            for (int j = 0; j < 2; ++j) {
                int ub = nq*16 + j*8 + 2*tig;
                float h0 = sm[HST_F + row*STRIDE_H + ub];
                float h1 = sm[HST_F + row*STRIDE_H + ub + 1];
                cst2[mt*8 + rh*4 + j*2]     = h0;
                cst2[mt*8 + rh*4 + j*2 + 1] = h1;
                *(uint32_t*)(smc + row*AROW_B + ub*2) = pkbf2(h0, h1);
            }
        }
    }
    #pragma unroll
    for (int i = 0; i < 16; ++i) cst[i] = cst2[i];

    float4 prev;
    if (tid < 128) {
        prev = ((const float4*)init_state)[grow];
        stage_in(smc, 0, tid, prev);
    }
    const float* wc0 = sm + WC_F;
    const float* wc1 = sm + WC_F + 64;
    float* rec = out + (size_t)(blockIdx.x*128 + tid)*(Tn*4);   // valid for tid<128

    // ---------------- decoder loop ----------------
    #pragma unroll 1
    for (int t = 0; t < Tn; ++t) {
        __syncthreads();
        const int pB = (t & 1) * ABUF_B;
        const int qB = ABUF_B - pB;
        float acc[2][4][8];
        #pragma unroll
        for (int i = 0; i < 2; ++i)
            #pragma unroll
            for (int g = 0; g < 4; ++g)
                #pragma unroll
                for (int j = 0; j < 8; ++j) acc[i][g][j] = 0.f;
        #pragma unroll
        for (int kt = 0; kt < 5; ++kt) {
            uint32_t a0H[4], a1H[4];
            ldm4(a0H, aB0H + pB + kt*32);
            ldm4(a1H, aB1H + pB + kt*32);
            #pragma unroll
            for (int g = 0; g < 4; ++g) {
                uint32_t bH[4];
                ldm4(bH, bBase0 + (uint32_t)(g*64*AROW_B + kt*32));
                mma_bf16(&acc[0][g][0], a0H, bH[0], bH[1]);
                mma_bf16(&acc[0][g][4], a0H, bH[2], bH[3]);
                mma_bf16(&acc[1][g][0], a1H, bH[0], bH[1]);
                mma_bf16(&acc[1][g][4], a1H, bH[2], bH[3]);
            }
        }
        // epilogue: gates -> h, W_c partials, store other buffer
        float pa[8];
        #pragma unroll
        for (int i = 0; i < 8; ++i) pa[i] = 0.f;
        #pragma unroll
        for (int mt = 0; mt < 2; ++mt) {
            #pragma unroll
            for (int rh = 0; rh < 2; ++rh) {
                int row = mq*32 + mt*16 + rh*8 + gid;
                #pragma unroll
                for (int j = 0; j < 2; ++j) {
                    float hh[2];
                    #pragma unroll
                    for (int e = 0; e < 2; ++e) {
                        int u = nq*16 + j*8 + 2*tig + e;
                        int fi = j*4 + rh*2 + e;
                        float ai = acc[mt][0][fi];
                        float af = acc[mt][1][fi];
                        float ag = acc[mt][2][fi];
                        float ao = acc[mt][3][fi];
                        int ci = mt*8 + rh*4 + j*2 + e;
                        float c = sig_hw(af)*cst[ci] + sig_hw(ai)*tanh_hw(ag);
                        cst[ci] = c;
                        float h = sig_hw(ao)*tanh_hw(c);
                        hh[e] = h;
                        pa[(mt*2+rh)*2+0] = fmaf(h, wc0[u], pa[(mt*2+rh)*2+0]);
                        pa[(mt*2+rh)*2+1] = fmaf(h, wc1[u], pa[(mt*2+rh)*2+1]);
                    }
                    int ub = nq*16 + j*8 + 2*tig;
                    *(uint32_t*)(smc + qB + row*AROW_B + ub*2) = pkbf2(hh[0], hh[1]);
                }
            }
        }
        #pragma unroll
        for (int i = 0; i < 8; ++i) {
            pa[i] += __shfl_xor_sync(0xFFFFFFFFu, pa[i], 1);
            pa[i] += __shfl_xor_sync(0xFFFFFFFFu, pa[i], 2);
        }
        if (tig == 0) {
            #pragma unroll
            for (int mt = 0; mt < 2; ++mt) {
                #pragma unroll
                for (int rh = 0; rh < 2; ++rh) {
                    int row = mq*32 + mt*16 + rh*8 + gid;
                    part[row*8 + nq*2 + 0] = pa[(mt*2+rh)*2+0];
                    part[row*8 + nq*2 + 1] = pa[(mt*2+rh)*2+1];
                }
            }
        }
        __syncthreads();
        if (tid < 128) {
            float a0 = part[tid*8+0] + part[tid*8+2] + part[tid*8+4] + part[tid*8+6] + sm[WC_F+128];
            float a1 = part[tid*8+1] + part[tid*8+3] + part[tid*8+5] + part[tid*8+7] + sm[WC_F+129];
            float steer = fminf(fmaxf(a1, -0.5f), 0.5f);
            float x = prev.x, y = prev.y, psi = prev.z, v = prev.w;
            float v1 = fminf(fmaxf(fmaf(a0, DTC, v), 0.0f), 30.0f);
            float pd = fminf(fmaxf(v * __tanf(steer) * (1.0f/2.5f), -1.57f), 1.57f);
            float s, c; __sincosf(psi, &s, &c);
            float4 cur = make_float4(fmaf(v*c, DTC, x), fmaf(v*s, DTC, y), fmaf(pd, DTC, psi), v1);
            *(float4*)(rec + t*4) = cur;
            if (t < Tn-1) stage_in(smc, qB, tid, cur);
            prev = cur;
        }
    }
}

extern "C" void kernel_launch(void* const* d_in, const int* in_sizes, int n_in,
                              void* d_out, int out_size)
{
    const float* expert     = (const float*)d_in[0];
    const float* init_state = (const float*)d_in[1];
    const float* eps        = (const float*)d_in[2];
    const float* W_se       = (const float*)d_in[3];
    const float* b_se       = (const float*)d_in[4];
    const float* W_ih_e     = (const float*)d_in[5];
    const float* W_hh_e     = (const float*)d_in[6];
    const float* b_ih_e     = (const float*)d_in[7];
    const float* b_hh_e     = (const float*)d_in[8];
    const float* mean_Ws    = (const float*)d_in[9];
    const float* mean_bs    = (const float*)d_in[10];
    const float* mean_Wf    = (const float*)d_in[11];
    const float* mean_bf    = (const float*)d_in[12];
    const float* lv_Ws      = (const float*)d_in[13];
    const float* lv_bs      = (const float*)d_in[14];
    const float* lv_Wf      = (const float*)d_in[15];
    const float* lv_bf      = (const float*)d_in[16];
    const float* W_init     = (const float*)d_in[17];
    const float* b_init     = (const float*)d_in[18];
    const float* W_ih_d     = (const float*)d_in[19];
    const float* W_hh_d     = (const float*)d_in[20];
    const float* b_ih_d     = (const float*)d_in[21];
    const float* b_hh_d     = (const float*)d_in[22];
    const float* W_c        = (const float*)d_in[23];
    const float* b_c        = (const float*)d_in[24];
    float* out = (float*)d_out;

    cudaFuncSetAttribute(vae_kernel, cudaFuncAttributeMaxDynamicSharedMemorySize, SMEM_BYTES);

    setup_kernel<<<256, 256>>>(W_se, b_se, W_ih_e, W_hh_e, b_ih_e, b_hh_e,
                               W_ih_d, W_hh_d, b_ih_d, b_hh_d,
                               (const float4*)expert, (float4*)(out + OFF_EXP));
    vae_kernel<<<NB, NT, SMEM_BYTES>>>(expert, init_state, eps,
        mean_Ws, mean_bs, mean_Wf, mean_bf,
        lv_Ws, lv_bs, lv_Wf, lv_bf,
        W_init, b_init, W_c, b_c, out);
}